// round 3
// baseline (speedup 1.0000x reference)
#include <cuda_runtime.h>
#include <math.h>

#define T_DATA 40000
#define SUB    32
#define EE     2000
#define EI     400
#define TAPS   200
#define NCOS   17
#define CBT    2048   // conv tile (outputs per block), 256 thr * 8

// ---------------- device scratch (no allocations allowed) ----------------
__device__ float  g_syn_e[SUB * T_DATA];
__device__ float  g_syn_i[SUB * T_DATA];
__device__ float  g_syn[(SUB + 1) * T_DATA];   // ch 0..31 subunit drive, ch 32 = hist_filt
__device__ float  g_zout[T_DATA];
__device__ float  g_ek[SUB * TAPS];
__device__ float  g_ik[SUB * TAPS];
__device__ float  g_hk[TAPS];
__device__ float  g_ok[TAPS];
__device__ float  g_cw[SUB * SUB];             // C_den[i][j] * exp(W_sub[j])
__device__ float2 g_lut_e[EE];                 // (weight, bitcast subunit)
__device__ float2 g_lut_i[EI];

// ---------------- f32x2 helpers (sm_103a packed fp32) ----------------
__device__ __forceinline__ unsigned long long pk2(float2 v) {
    unsigned long long r;
    asm("mov.b64 %0, {%1, %2};" : "=l"(r) : "f"(v.x), "f"(v.y));
    return r;
}
__device__ __forceinline__ void fma2(unsigned long long& d, unsigned long long a,
                                     unsigned long long b) {
    asm("fma.rn.f32x2 %0, %1, %2, %0;" : "+l"(d) : "l"(a), "l"(b));
}
__device__ __forceinline__ float unpk_sum(unsigned long long v) {
    float lo, hi;
    asm("mov.b64 {%0, %1}, %2;" : "=f"(lo), "=f"(hi) : "l"(v));
    return lo + hi;
}

// ---------------- K0: prep — LUTs, kernels, tree weights, out_filters ----------------
__global__ void prep_kernel(const float* __restrict__ C_den,
                            const float* __restrict__ Cse,
                            const float* __restrict__ Csi,
                            const float* __restrict__ Tau,
                            const float* __restrict__ Delta,
                            const float* __restrict__ Wsyn,
                            const float* __restrict__ Wsub,
                            const float* __restrict__ Whist,
                            const float* __restrict__ TauOut,
                            const float* __restrict__ Wout,
                            float* __restrict__ d_out, int out_size) {
    const int tid = threadIdx.x;

    // one-hot column -> (subunit, weight). Columns in this problem have exactly
    // one nonzero; take the last one found (0-weight if empty -> harmless add of 0).
    for (int e = tid; e < EE; e += 256) {
        int s0 = 0; float w = 0.f;
        for (int s = 0; s < SUB; s++) {
            float c = Cse[s * EE + e];
            if (c != 0.f) { s0 = s; w = c; }
        }
        g_lut_e[e] = make_float2(w, __int_as_float(s0));
    }
    for (int e = tid; e < EI; e += 256) {
        int s0 = 0; float w = 0.f;
        for (int s = 0; s < SUB; s++) {
            float c = Csi[s * EI + e];
            if (c != 0.f) { s0 = s; w = c; }
        }
        g_lut_i[e] = make_float2(w, __int_as_float(s0));
    }

    // alpha kernels (e/i) + out_filters rows
    for (int idx = tid; idx < SUB * TAPS; idx += 256) {
        const int s = idx / TAPS, u = idx % TAPS;
        const float tf = (float)u;
        float te  = fmaxf(tf - expf(Delta[s * 2 + 0]), 0.f);
        float tte = te / expf(Tau[s * 2 + 0]);
        float ek  = tte * expf(-tte) * expf(Wsyn[s * 2 + 0]);
        float ti  = fmaxf(tf - expf(Delta[s * 2 + 1]), 0.f);
        float tti = ti / expf(Tau[s * 2 + 1]);
        float ik  = -tti * expf(-tti) * expf(Wsyn[s * 2 + 1]);
        g_ek[idx] = ek;
        g_ik[idx] = ik;
        const int base = 2 * T_DATA;
        if (base + idx < out_size)                   d_out[base + idx] = ek;
        if (base + SUB * TAPS + idx < out_size)      d_out[base + SUB * TAPS + idx] = ik;
    }

    // history kernel from raised-cosine basis
    for (int u = tid; u < TAPS; u += 256) {
        const float raw = 4.0f * logf((float)u + 1.0f);
        const float pi_f    = 3.14159274101257324f;  // float(pi)
        const float half_pi = 1.57079637050628662f;  // float(pi/2)
        float hk = 0.f;
        for (int n = 0; n < NCOS; n++) {
            float phi = half_pi * (float)n;
            float b = 0.f;
            if (raw >= phi - pi_f && raw <= phi + pi_f)
                b = 0.5f * cosf(raw - phi) + 0.5f;
            hk -= expf(Whist[n]) * b;
        }
        g_hk[u] = hk;
        const int base = 2 * T_DATA + 2 * SUB * TAPS;
        if (base + u < out_size) d_out[base + u] = hk;
    }

    // output alpha kernel
    for (int u = tid; u < TAPS; u += 256) {
        float tto = (float)u / expf(TauOut[0]);
        g_ok[u] = tto * expf(-tto) * expf(Wout[0]);
    }

    // tree weights
    for (int idx = tid; idx < SUB * SUB; idx += 256) {
        int j = idx % SUB;
        g_cw[idx] = C_den[idx] * expf(Wsub[j]);
    }
}

// ---------------- K1: spike projection  S @ Csyn^T  (one-hot scatter) ----------------
#define PBT 16  // timesteps per block
__global__ void proj_kernel(const float* __restrict__ Se, const float* __restrict__ Si) {
    __shared__ float acc_e[PBT][SUB + 1];
    __shared__ float acc_i[PBT][SUB + 1];
    const int tid = threadIdx.x;
    for (int i = tid; i < PBT * (SUB + 1); i += 256) {
        (&acc_e[0][0])[i] = 0.f;
        (&acc_i[0][0])[i] = 0.f;
    }
    __syncthreads();

    const int t0 = blockIdx.x * PBT;
    const float4* Se4 = reinterpret_cast<const float4*>(Se);
    const float4* Si4 = reinterpret_cast<const float4*>(Si);

    // excitatory: PBT rows x (EE/4) float4
    const int EROW = EE / 4;  // 500
    #pragma unroll 2
    for (int idx = tid; idx < PBT * EROW; idx += 256) {
        const int tl = idx / EROW, c4 = idx % EROW;
        const float4 v = Se4[(size_t)(t0 + tl) * EROW + c4];
        if (v.x != 0.f) { float2 p = g_lut_e[c4 * 4 + 0]; atomicAdd(&acc_e[tl][__float_as_int(p.y)], v.x * p.x); }
        if (v.y != 0.f) { float2 p = g_lut_e[c4 * 4 + 1]; atomicAdd(&acc_e[tl][__float_as_int(p.y)], v.y * p.x); }
        if (v.z != 0.f) { float2 p = g_lut_e[c4 * 4 + 2]; atomicAdd(&acc_e[tl][__float_as_int(p.y)], v.z * p.x); }
        if (v.w != 0.f) { float2 p = g_lut_e[c4 * 4 + 3]; atomicAdd(&acc_e[tl][__float_as_int(p.y)], v.w * p.x); }
    }
    // inhibitory: PBT rows x (EI/4) float4
    const int IROW = EI / 4;  // 100
    for (int idx = tid; idx < PBT * IROW; idx += 256) {
        const int tl = idx / IROW, c4 = idx % IROW;
        const float4 v = Si4[(size_t)(t0 + tl) * IROW + c4];
        if (v.x != 0.f) { float2 p = g_lut_i[c4 * 4 + 0]; atomicAdd(&acc_i[tl][__float_as_int(p.y)], v.x * p.x); }
        if (v.y != 0.f) { float2 p = g_lut_i[c4 * 4 + 1]; atomicAdd(&acc_i[tl][__float_as_int(p.y)], v.y * p.x); }
        if (v.z != 0.f) { float2 p = g_lut_i[c4 * 4 + 2]; atomicAdd(&acc_i[tl][__float_as_int(p.y)], v.z * p.x); }
        if (v.w != 0.f) { float2 p = g_lut_i[c4 * 4 + 3]; atomicAdd(&acc_i[tl][__float_as_int(p.y)], v.w * p.x); }
    }
    __syncthreads();

    // write transposed [sub][t] layout for the conv
    for (int idx = tid; idx < SUB * PBT; idx += 256) {
        const int s = idx / PBT, tl = idx % PBT;
        g_syn_e[s * T_DATA + t0 + tl] = acc_e[tl][s];
        g_syn_i[s * T_DATA + t0 + tl] = acc_i[tl][s];
    }
}

// ---------------- K2: 33-channel 200-tap causal conv (f32x2 packed, sliding window) ----
__global__ void conv_kernel(const float* __restrict__ Z) {
    __shared__ float2 sig[CBT + TAPS];  // index i <-> global t = t0 - TAPS + i
    __shared__ float2 kk[TAPS];
    const int ch  = blockIdx.y;
    const int t0  = blockIdx.x * CBT;
    const int tid = threadIdx.x;
    const bool has_i = (ch < SUB);

    const float* pe = has_i ? (g_syn_e + ch * T_DATA) : Z;
    const float* pi = has_i ? (g_syn_i + ch * T_DATA) : nullptr;
    const float* ke = has_i ? (g_ek + ch * TAPS) : g_hk;
    const float* ki = has_i ? (g_ik + ch * TAPS) : nullptr;

    for (int i = tid; i < CBT + TAPS; i += 256) {
        const int t = t0 - TAPS + i;
        const bool ok = (t >= 0) && (t < T_DATA);
        float a = ok ? pe[t] : 0.f;
        float b = (ok && has_i) ? pi[t] : 0.f;
        sig[i] = make_float2(a, b);
    }
    for (int u = tid; u < TAPS; u += 256)
        kk[u] = make_float2(ke[u], has_i ? ki[u] : 0.f);
    __syncthreads();

    const int base = tid * 8;  // first output (tile-local)
    unsigned long long acc[8];
    unsigned long long w[8];
    #pragma unroll
    for (int r = 0; r < 8; r++) acc[r] = 0ull;
    // preload window for tap u=0: need sig[base + 199 + r]
    #pragma unroll
    for (int r = 0; r < 8; r++) w[(7 + r) & 7] = pk2(sig[base + 199 + r]);

    for (int g = 0; g < TAPS; g += 8) {
        #pragma unroll
        for (int c = 0; c < 8; c++) {
            const int u = g + c;
            if (u > 0) w[(7 - c) & 7] = pk2(sig[base + 199 - u]);  // new value (r=0)
            const unsigned long long k2 = pk2(kk[u]);
            #pragma unroll
            for (int r = 0; r < 8; r++)
                fma2(acc[r], k2, w[(7 - c + r) & 7]);
        }
    }

    #pragma unroll
    for (int r = 0; r < 8; r++) {
        const int t = t0 + base + r;
        if (t < T_DATA) g_syn[ch * T_DATA + t] = unpk_sum(acc[r]);
    }
}

// ---------------- K3: tree walk + heaviside (parallel over t) ----------------
__global__ void tree_kernel(const float* __restrict__ Theta,
                            float* __restrict__ d_out, int out_size) {
    __shared__ float cw[SUB * SUB];
    __shared__ float th[SUB];
    const int tid = threadIdx.x;
    for (int i = tid; i < SUB * SUB; i += 256) cw[i] = g_cw[i];
    if (tid < SUB) th[tid] = Theta[tid];
    __syncthreads();

    const int t = blockIdx.x * 256 + tid;
    if (t >= T_DATA) return;

    float v[SUB];
    #pragma unroll
    for (int s = 0; s < SUB; s++) v[s] = g_syn[s * T_DATA + t];

    // children always have larger index; in-place update is exact (untouched
    // entries of sub_out are 0 at the time the reference reads them)
    #pragma unroll
    for (int idx = SUB - 1; idx >= 1; idx--) {
        float a = v[idx] + th[idx];
        #pragma unroll
        for (int j = idx + 1; j < SUB; j++)
            a = fmaf(cw[idx * SUB + j], v[j], a);
        v[idx] = tanhf(a);
    }
    float zin = g_syn[SUB * T_DATA + t] + v[0] + th[0];  // hist_filt + syn[:,0] + Theta[0]
    #pragma unroll
    for (int j = 1; j < SUB; j++)
        zin = fmaf(cw[j], v[j], zin);  // root children (sub_out[:,0] == 0)

    const float zo = (zin > 0.f) ? 1.f : 0.f;
    g_zout[t] = zo;
    if (T_DATA + t < out_size) d_out[T_DATA + t] = zo;
}

// ---------------- K4: output alpha-kernel conv of Z_out -> V_out ----------------
__global__ void vconv_kernel(float* __restrict__ d_out, int out_size) {
    __shared__ float sig[CBT + TAPS];
    __shared__ float kern[TAPS];
    const int t0  = blockIdx.x * CBT;
    const int tid = threadIdx.x;
    for (int i = tid; i < CBT + TAPS; i += 256) {
        const int t = t0 - TAPS + i;
        sig[i] = (t >= 0 && t < T_DATA) ? g_zout[t] : 0.f;
    }
    for (int u = tid; u < TAPS; u += 256) kern[u] = g_ok[u];
    __syncthreads();

    const int base = tid * 8;
    float acc[8] = {0.f, 0.f, 0.f, 0.f, 0.f, 0.f, 0.f, 0.f};
    for (int u = 0; u < TAPS; u++) {
        const float k = kern[u];
        #pragma unroll
        for (int r = 0; r < 8; r++)
            acc[r] = fmaf(k, sig[base + 199 - u + r], acc[r]);
    }
    #pragma unroll
    for (int r = 0; r < 8; r++) {
        const int t = t0 + base + r;
        if (t < T_DATA && t < out_size) d_out[t] = acc[r];
    }
}

// ---------------- launch ----------------
extern "C" void kernel_launch(void* const* d_in, const int* in_sizes, int n_in,
                              void* d_out, int out_size) {
    const float* S_e    = (const float*)d_in[0];
    const float* S_i    = (const float*)d_in[1];
    const float* Z      = (const float*)d_in[2];
    const float* C_den  = (const float*)d_in[3];
    const float* Cse    = (const float*)d_in[4];
    const float* Csi    = (const float*)d_in[5];
    const float* Tau    = (const float*)d_in[6];
    const float* Delta  = (const float*)d_in[7];
    const float* Wsyn   = (const float*)d_in[8];
    const float* Wsub   = (const float*)d_in[9];
    const float* Whist  = (const float*)d_in[10];
    const float* Theta  = (const float*)d_in[11];
    const float* TauOut = (const float*)d_in[12];
    const float* Wout   = (const float*)d_in[13];
    float* out = (float*)d_out;

    prep_kernel<<<1, 256>>>(C_den, Cse, Csi, Tau, Delta, Wsyn, Wsub, Whist,
                            TauOut, Wout, out, out_size);
    proj_kernel<<<T_DATA / PBT, 256>>>(S_e, S_i);
    const int ctiles = (T_DATA + CBT - 1) / CBT;  // 20
    conv_kernel<<<dim3(ctiles, SUB + 1), 256>>>(Z);
    tree_kernel<<<(T_DATA + 255) / 256, 256>>>(Theta, out, out_size);
    vconv_kernel<<<ctiles, 256>>>(out, out_size);
}

// round 4
// speedup vs baseline: 1.2244x; 1.2244x over previous
#include <cuda_runtime.h>
#include <math.h>

#define T_DATA 40000
#define SUB    32
#define EE     2000
#define EI     400
#define TAPS   200
#define NCOS   17
#define CBT    2048   // conv tile (outputs per block), 256 thr * 8
#define VBT    512    // vconv tile

// padded smem index: +1 float2 per 8 -> per-thread stride 9 elems = 72B -> 2-way conflict
#define PX(i) ((i) + ((i) >> 3))

// ---------------- device scratch (no allocations allowed) ----------------
__device__ float  g_syn_e[SUB * T_DATA];
__device__ float  g_syn_i[SUB * T_DATA];
__device__ float  g_syn[(SUB + 1) * T_DATA];   // ch 0..31 subunit drive, ch 32 = hist_filt
__device__ float  g_zout[T_DATA];
__device__ float  g_ek[SUB * TAPS];
__device__ float  g_ik[SUB * TAPS];
__device__ float  g_hk[TAPS];
__device__ float  g_ok[TAPS];
__device__ float  g_cw[SUB * SUB];             // C_den[i][j] * exp(W_sub[j])
__device__ int    g_chn[SUB * 2];              // up to 2 children per node (binary tree)
__device__ float  g_chw[SUB * 2];
__device__ float2 g_lut_e[EE];                 // (weight, bitcast subunit)
__device__ float2 g_lut_i[EI];

// ---------------- f32x2 helpers (sm_103a packed fp32) ----------------
__device__ __forceinline__ unsigned long long pk2(float2 v) {
    unsigned long long r;
    asm("mov.b64 %0, {%1, %2};" : "=l"(r) : "f"(v.x), "f"(v.y));
    return r;
}
__device__ __forceinline__ void fma2(unsigned long long& d, unsigned long long a,
                                     unsigned long long b) {
    asm("fma.rn.f32x2 %0, %1, %2, %0;" : "+l"(d) : "l"(a), "l"(b));
}
__device__ __forceinline__ float unpk_sum(unsigned long long v) {
    float lo, hi;
    asm("mov.b64 {%0, %1}, %2;" : "=f"(lo), "=f"(hi) : "l"(v));
    return lo + hi;
}

// branchless tanh via expf (straight-line -> ILP across independent tree nodes)
__device__ __forceinline__ float tanh_b(float x) {
    float e = expf(-2.0f * fabsf(x));
    float r = (1.0f - e) / (1.0f + e);
    return copysignf(r, x);
}

// ---------------- K0: prep — LUTs, kernels, tree weights, out_filters ----------------
__global__ void prep_kernel(const float* __restrict__ C_den,
                            const float* __restrict__ Cse,
                            const float* __restrict__ Csi,
                            const float* __restrict__ Tau,
                            const float* __restrict__ Delta,
                            const float* __restrict__ Wsyn,
                            const float* __restrict__ Wsub,
                            const float* __restrict__ Whist,
                            const float* __restrict__ TauOut,
                            const float* __restrict__ Wout,
                            float* __restrict__ d_out, int out_size) {
    const int tid = threadIdx.x;

    // one-hot column -> (subunit, weight)
    for (int e = tid; e < EE; e += 256) {
        int s0 = 0; float w = 0.f;
        for (int s = 0; s < SUB; s++) {
            float c = Cse[s * EE + e];
            if (c != 0.f) { s0 = s; w = c; }
        }
        g_lut_e[e] = make_float2(w, __int_as_float(s0));
    }
    for (int e = tid; e < EI; e += 256) {
        int s0 = 0; float w = 0.f;
        for (int s = 0; s < SUB; s++) {
            float c = Csi[s * EI + e];
            if (c != 0.f) { s0 = s; w = c; }
        }
        g_lut_i[e] = make_float2(w, __int_as_float(s0));
    }

    // alpha kernels (e/i) + out_filters rows
    for (int idx = tid; idx < SUB * TAPS; idx += 256) {
        const int s = idx / TAPS, u = idx % TAPS;
        const float tf = (float)u;
        float te  = fmaxf(tf - expf(Delta[s * 2 + 0]), 0.f);
        float tte = te / expf(Tau[s * 2 + 0]);
        float ek  = tte * expf(-tte) * expf(Wsyn[s * 2 + 0]);
        float ti  = fmaxf(tf - expf(Delta[s * 2 + 1]), 0.f);
        float tti = ti / expf(Tau[s * 2 + 1]);
        float ik  = -tti * expf(-tti) * expf(Wsyn[s * 2 + 1]);
        g_ek[idx] = ek;
        g_ik[idx] = ik;
        const int base = 2 * T_DATA;
        if (base + idx < out_size)              d_out[base + idx] = ek;
        if (base + SUB * TAPS + idx < out_size) d_out[base + SUB * TAPS + idx] = ik;
    }

    // history kernel from raised-cosine basis
    for (int u = tid; u < TAPS; u += 256) {
        const float raw = 4.0f * logf((float)u + 1.0f);
        const float pi_f    = 3.14159274101257324f;
        const float half_pi = 1.57079637050628662f;
        float hk = 0.f;
        for (int n = 0; n < NCOS; n++) {
            float phi = half_pi * (float)n;
            float b = 0.f;
            if (raw >= phi - pi_f && raw <= phi + pi_f)
                b = 0.5f * cosf(raw - phi) + 0.5f;
            hk -= expf(Whist[n]) * b;
        }
        g_hk[u] = hk;
        const int base = 2 * T_DATA + 2 * SUB * TAPS;
        if (base + u < out_size) d_out[base + u] = hk;
    }

    // output alpha kernel
    for (int u = tid; u < TAPS; u += 256) {
        float tto = (float)u / expf(TauOut[0]);
        g_ok[u] = tto * expf(-tto) * expf(Wout[0]);
    }

    // tree weights
    for (int idx = tid; idx < SUB * SUB; idx += 256) {
        int j = idx % SUB;
        g_cw[idx] = C_den[idx] * expf(Wsub[j]);
    }
    __syncthreads();

    // extract per-node children (binary dendrite tree: <= 2 children, larger index)
    if (tid < SUB) {
        int c0 = 0, c1 = 0; float w0 = 0.f, w1 = 0.f; int cnt = 0;
        for (int j = tid + 1; j < SUB; j++) {
            float w = g_cw[tid * SUB + j];
            if (w != 0.f) {
                if (cnt == 0) { c0 = j; w0 = w; }
                else          { c1 = j; w1 = w; }
                cnt++;
            }
        }
        g_chn[tid * 2 + 0] = c0;  g_chw[tid * 2 + 0] = w0;
        g_chn[tid * 2 + 1] = c1;  g_chw[tid * 2 + 1] = w1;
    }
}

// ---------------- K1: spike projection  S @ Csyn^T  (one-hot scatter) ----------------
#define PBT 16  // timesteps per block
__global__ void proj_kernel(const float* __restrict__ Se, const float* __restrict__ Si) {
    __shared__ float acc_e[PBT][SUB + 1];
    __shared__ float acc_i[PBT][SUB + 1];
    const int tid = threadIdx.x;
    for (int i = tid; i < PBT * (SUB + 1); i += 256) {
        (&acc_e[0][0])[i] = 0.f;
        (&acc_i[0][0])[i] = 0.f;
    }
    __syncthreads();

    const int t0 = blockIdx.x * PBT;
    const float4* Se4 = reinterpret_cast<const float4*>(Se);
    const float4* Si4 = reinterpret_cast<const float4*>(Si);

    const int EROW = EE / 4;  // 500
    #pragma unroll 2
    for (int idx = tid; idx < PBT * EROW; idx += 256) {
        const int tl = idx / EROW, c4 = idx % EROW;
        const float4 v = Se4[(size_t)(t0 + tl) * EROW + c4];
        if (v.x != 0.f) { float2 p = g_lut_e[c4 * 4 + 0]; atomicAdd(&acc_e[tl][__float_as_int(p.y)], v.x * p.x); }
        if (v.y != 0.f) { float2 p = g_lut_e[c4 * 4 + 1]; atomicAdd(&acc_e[tl][__float_as_int(p.y)], v.y * p.x); }
        if (v.z != 0.f) { float2 p = g_lut_e[c4 * 4 + 2]; atomicAdd(&acc_e[tl][__float_as_int(p.y)], v.z * p.x); }
        if (v.w != 0.f) { float2 p = g_lut_e[c4 * 4 + 3]; atomicAdd(&acc_e[tl][__float_as_int(p.y)], v.w * p.x); }
    }
    const int IROW = EI / 4;  // 100
    for (int idx = tid; idx < PBT * IROW; idx += 256) {
        const int tl = idx / IROW, c4 = idx % IROW;
        const float4 v = Si4[(size_t)(t0 + tl) * IROW + c4];
        if (v.x != 0.f) { float2 p = g_lut_i[c4 * 4 + 0]; atomicAdd(&acc_i[tl][__float_as_int(p.y)], v.x * p.x); }
        if (v.y != 0.f) { float2 p = g_lut_i[c4 * 4 + 1]; atomicAdd(&acc_i[tl][__float_as_int(p.y)], v.y * p.x); }
        if (v.z != 0.f) { float2 p = g_lut_i[c4 * 4 + 2]; atomicAdd(&acc_i[tl][__float_as_int(p.y)], v.z * p.x); }
        if (v.w != 0.f) { float2 p = g_lut_i[c4 * 4 + 3]; atomicAdd(&acc_i[tl][__float_as_int(p.y)], v.w * p.x); }
    }
    __syncthreads();

    for (int idx = tid; idx < SUB * PBT; idx += 256) {
        const int s = idx / PBT, tl = idx % PBT;
        g_syn_e[s * T_DATA + t0 + tl] = acc_e[tl][s];
        g_syn_i[s * T_DATA + t0 + tl] = acc_i[tl][s];
    }
}

// ---------------- K2: 33-ch 200-tap causal conv (f32x2 packed, padded smem) ----------
__global__ void conv_kernel(const float* __restrict__ Z) {
    __shared__ float2 sig[PX(CBT + TAPS - 1) + 2];  // padded: kills 16-way conflict
    __shared__ float2 kk[TAPS];
    const int ch  = blockIdx.y;
    const int t0  = blockIdx.x * CBT;
    const int tid = threadIdx.x;
    const bool has_i = (ch < SUB);

    const float* pe = has_i ? (g_syn_e + ch * T_DATA) : Z;
    const float* pi = has_i ? (g_syn_i + ch * T_DATA) : nullptr;
    const float* ke = has_i ? (g_ek + ch * TAPS) : g_hk;
    const float* ki = has_i ? (g_ik + ch * TAPS) : nullptr;

    for (int i = tid; i < CBT + TAPS; i += 256) {
        const int t = t0 - TAPS + i;
        const bool ok = (t >= 0) && (t < T_DATA);
        float a = ok ? pe[t] : 0.f;
        float b = (ok && has_i) ? pi[t] : 0.f;
        sig[PX(i)] = make_float2(a, b);
    }
    for (int u = tid; u < TAPS; u += 256)
        kk[u] = make_float2(ke[u], has_i ? ki[u] : 0.f);
    __syncthreads();

    const int base = tid * 8;  // first output (tile-local)
    unsigned long long acc[8];
    unsigned long long w[8];
    #pragma unroll
    for (int r = 0; r < 8; r++) acc[r] = 0ull;
    #pragma unroll
    for (int r = 0; r < 8; r++) w[(7 + r) & 7] = pk2(sig[PX(base + 199 + r)]);

    for (int g = 0; g < TAPS; g += 8) {
        #pragma unroll
        for (int c = 0; c < 8; c++) {
            const int u = g + c;
            if (u > 0) w[(7 - c) & 7] = pk2(sig[PX(base + 199 - u)]);
            const unsigned long long k2 = pk2(kk[u]);
            #pragma unroll
            for (int r = 0; r < 8; r++)
                fma2(acc[r], k2, w[(7 - c + r) & 7]);
        }
    }

    #pragma unroll
    for (int r = 0; r < 8; r++) {
        const int t = t0 + base + r;
        if (t < T_DATA) g_syn[ch * T_DATA + t] = unpk_sum(acc[r]);
    }
}

// ---------------- K3: tree walk, level-parallel (5 tanh deps, not 31) -------------
__global__ void tree_kernel(const float* __restrict__ Theta,
                            float* __restrict__ d_out, int out_size) {
    __shared__ float th[SUB];
    __shared__ int   chn[SUB * 2];
    __shared__ float chw[SUB * 2];
    const int tid = threadIdx.x;
    if (tid < SUB) th[tid] = Theta[tid];
    if (tid < SUB * 2) { chn[tid] = g_chn[tid]; chw[tid] = g_chw[tid]; }
    __syncthreads();

    const int t = blockIdx.x * 256 + tid;
    if (t >= T_DATA) return;

    float v[SUB];
    #pragma unroll
    for (int s = 0; s < SUB; s++) v[s] = g_syn[s * T_DATA + t];

    // binary tree: children of idx are in strictly later level batches.
    // Process batches [16,31] -> [8,15] -> [4,7] -> [2,3] -> [1]; each batch's
    // nodes are independent -> ILP hides the expf/div latency.
    #define TSTEP(idx)                                                        \
        v[idx] = tanh_b(fmaf(chw[2*(idx)+1], v[chn[2*(idx)+1]],               \
                        fmaf(chw[2*(idx)],   v[chn[2*(idx)]],                 \
                             v[idx] + th[idx])));
    #pragma unroll
    for (int i = 16; i < 32; i++) TSTEP(i)
    #pragma unroll
    for (int i = 8; i < 16; i++) TSTEP(i)
    #pragma unroll
    for (int i = 4; i < 8; i++) TSTEP(i)
    #pragma unroll
    for (int i = 2; i < 4; i++) TSTEP(i)
    TSTEP(1)
    #undef TSTEP

    float zin = g_syn[SUB * T_DATA + t] + v[0] + th[0];   // hist + syn[:,0] + Theta[0]
    zin = fmaf(chw[0], v[chn[0]], zin);
    zin = fmaf(chw[1], v[chn[1]], zin);

    const float zo = (zin > 0.f) ? 1.f : 0.f;
    g_zout[t] = zo;
    if (T_DATA + t < out_size) d_out[T_DATA + t] = zo;
}

// ---------------- K4: output alpha-kernel conv of Z_out -> V_out ------------------
__global__ void vconv_kernel(float* __restrict__ d_out, int out_size) {
    __shared__ float sig[VBT + TAPS];
    __shared__ float kern[TAPS];
    const int t0  = blockIdx.x * VBT;
    const int tid = threadIdx.x;
    for (int i = tid; i < VBT + TAPS; i += 256) {
        const int t = t0 - TAPS + i;
        sig[i] = (t >= 0 && t < T_DATA) ? g_zout[t] : 0.f;
    }
    for (int u = tid; u < TAPS; u += 256) kern[u] = g_ok[u];
    __syncthreads();

    // interleaved outputs: lanes read consecutive floats -> conflict-free
    float a0 = 0.f, a1 = 0.f;
    for (int u = 0; u < TAPS; u++) {
        const float k = kern[u];
        a0 = fmaf(k, sig[tid + 199 - u], a0);
        a1 = fmaf(k, sig[tid + 256 + 199 - u], a1);
    }
    int t = t0 + tid;
    if (t < T_DATA && t < out_size) d_out[t] = a0;
    t += 256;
    if (t < T_DATA && t < out_size) d_out[t] = a1;
}

// ---------------- launch ----------------
extern "C" void kernel_launch(void* const* d_in, const int* in_sizes, int n_in,
                              void* d_out, int out_size) {
    const float* S_e    = (const float*)d_in[0];
    const float* S_i    = (const float*)d_in[1];
    const float* Z      = (const float*)d_in[2];
    const float* C_den  = (const float*)d_in[3];
    const float* Cse    = (const float*)d_in[4];
    const float* Csi    = (const float*)d_in[5];
    const float* Tau    = (const float*)d_in[6];
    const float* Delta  = (const float*)d_in[7];
    const float* Wsyn   = (const float*)d_in[8];
    const float* Wsub   = (const float*)d_in[9];
    const float* Whist  = (const float*)d_in[10];
    const float* Theta  = (const float*)d_in[11];
    const float* TauOut = (const float*)d_in[12];
    const float* Wout   = (const float*)d_in[13];
    float* out = (float*)d_out;

    prep_kernel<<<1, 256>>>(C_den, Cse, Csi, Tau, Delta, Wsyn, Wsub, Whist,
                            TauOut, Wout, out, out_size);
    proj_kernel<<<T_DATA / PBT, 256>>>(S_e, S_i);
    const int ctiles = (T_DATA + CBT - 1) / CBT;  // 20
    conv_kernel<<<dim3(ctiles, SUB + 1), 256>>>(Z);
    tree_kernel<<<(T_DATA + 255) / 256, 256>>>(Theta, out, out_size);
    vconv_kernel<<<(T_DATA + VBT - 1) / VBT, 256>>>(out, out_size);
}